// round 1
// baseline (speedup 1.0000x reference)
#include <cuda_runtime.h>
#include <math.h>

// ---------------- problem constants ----------------
#define NROWS 50000   // nodes per graph (tweets / users) == VOCAB
#define NFEAT 300
#define LWORDS 16
#define EDGES 800000
#define HID 64
#define JOINT 128
#define BATCH 4096
#define ALPHA 0.2f
#define EPSV 1e-16f

// ---------------- scratch (device globals; no allocation allowed) ----------------
__device__ float g_bufA[(size_t)NROWS * HID];     // Pw / h1
__device__ float g_bufB[(size_t)NROWS * HID];     // h1 / out1
__device__ float g_bufC[(size_t)NROWS * JOINT];   // h2
__device__ float g_twX[(size_t)NROWS * JOINT];
__device__ float g_tuX[(size_t)NROWS * JOINT];
__device__ float g_fv[NROWS];
__device__ float g_gv[NROWS];
__device__ int   g_cnt[NROWS];
__device__ int   g_incl[NROWS];
__device__ int   g_rowptr[NROWS + 1];
__device__ int   g_tmp[NROWS];
__device__ int   g_cols[EDGES];
__device__ int   g_bsums[64];
__device__ int   g_bpre[64];
__device__ float g_att[2];

// ---------------- small utility kernels ----------------
__global__ void zero_att_k(float* att) {
    if (threadIdx.x < 2) att[threadIdx.x] = 0.0f;
}

__global__ void zero_int_k(int* p, int n) {
    int i = blockIdx.x * blockDim.x + threadIdx.x;
    if (i < n) p[i] = 0;
}

// ---------------- GEMM: C[M,N] = A[M,K] @ B[K,N]  (N == BN, grid.y == 1) ----------------
template <int BM, int BN, int BK, int TM, int TN, bool FUSE>
__global__ void gemm_k(const float* __restrict__ A, const float* __restrict__ Bm,
                       float* __restrict__ C, int M, int K,
                       const float* __restrict__ proj, float* __restrict__ red_out) {
    constexpr int TX = BN / TN;           // 16
    constexpr int TY = BM / TM;           // 16
    __shared__ __align__(16) float As[BM][BK + 1];
    __shared__ __align__(16) float Bs[BK][BN];

    int tid = threadIdx.x;
    int tx = tid % TX;
    int ty = tid / TX;
    int m0 = blockIdx.x * BM;

    float acc[TM][TN];
#pragma unroll
    for (int i = 0; i < TM; i++)
#pragma unroll
        for (int j = 0; j < TN; j++) acc[i][j] = 0.0f;

    int nk = (K + BK - 1) / BK;
    for (int kb = 0; kb < nk; kb++) {
        int k0 = kb * BK;
        // load A tile
#pragma unroll
        for (int t = tid; t < BM * BK; t += TX * TY) {
            int m = t / BK, k = t % BK;
            float v = 0.0f;
            if (m0 + m < M && k0 + k < K) v = A[(size_t)(m0 + m) * K + (k0 + k)];
            As[m][k] = v;
        }
        // load B tile (B row stride == BN == N)
#pragma unroll
        for (int t = tid; t < BK * BN; t += TX * TY) {
            int k = t / BN, n = t % BN;
            float v = 0.0f;
            if (k0 + k < K) v = Bm[(size_t)(k0 + k) * BN + n];
            Bs[k][n] = v;
        }
        __syncthreads();
#pragma unroll
        for (int k = 0; k < BK; k++) {
            float a[TM], b[TN];
#pragma unroll
            for (int i = 0; i < TM; i++) a[i] = As[ty * TM + i][k];
#pragma unroll
            for (int j = 0; j < TN; j += 4) {
                float4 b4 = *reinterpret_cast<const float4*>(&Bs[k][tx * TN + j]);
                b[j] = b4.x; b[j + 1] = b4.y; b[j + 2] = b4.z; b[j + 3] = b4.w;
            }
#pragma unroll
            for (int i = 0; i < TM; i++)
#pragma unroll
                for (int j = 0; j < TN; j++) acc[i][j] = fmaf(a[i], b[j], acc[i][j]);
        }
        __syncthreads();
    }

    if (!FUSE) {
#pragma unroll
        for (int i = 0; i < TM; i++) {
            int m = m0 + ty * TM + i;
            if (m < M) {
#pragma unroll
                for (int j = 0; j < TN; j += 4) {
                    float4 v4 = make_float4(acc[i][j], acc[i][j + 1], acc[i][j + 2], acc[i][j + 3]);
                    *reinterpret_cast<float4*>(&C[(size_t)m * BN + tx * TN + j]) = v4;
                }
            }
        }
    } else {
        // sum over tile of tanh(acc) * proj[col]; OOB rows contribute tanh(0)=0
        float s = 0.0f;
#pragma unroll
        for (int j = 0; j < TN; j++) {
            float pj = proj[tx * TN + j];
#pragma unroll
            for (int i = 0; i < TM; i++) s += tanhf(acc[i][j]) * pj;
        }
#pragma unroll
        for (int o = 16; o; o >>= 1) s += __shfl_xor_sync(0xffffffffu, s, o);
        __shared__ float wred[TX * TY / 32];
        if ((tid & 31) == 0) wred[tid >> 5] = s;
        __syncthreads();
        if (tid == 0) {
            float tot = 0.0f;
            for (int w = 0; w < TX * TY / 32; w++) tot += wred[w];
            atomicAdd(red_out, tot);
        }
    }
}

// ---------------- gather-mean: h[i][c] = mean_l Pw[idx[i][l]][c] ----------------
__global__ void gather_mean_k(const int* __restrict__ idx, const float* __restrict__ P,
                              float* __restrict__ out) {
    int i = blockIdx.x * 4 + threadIdx.y;
    int c = threadIdx.x;  // 0..63
    if (i >= NROWS) return;
    float acc = 0.0f;
#pragma unroll
    for (int l = 0; l < LWORDS; l++) {
        int w = idx[i * LWORDS + l];
        acc += P[(size_t)w * HID + c];
    }
    out[(size_t)i * HID + c] = acc * (1.0f / LWORDS);
}

// ---------------- per-node attention scalars: f = h@a[:D], g = h@a[D:] ----------------
template <int D>
__global__ void fg_k(const float* __restrict__ h, const float* __restrict__ a,
                     float* __restrict__ f, float* __restrict__ g) {
    int w = (blockIdx.x * blockDim.x + threadIdx.x) >> 5;
    int lane = threadIdx.x & 31;
    if (w >= NROWS) return;
    float sf = 0.0f, sg = 0.0f;
#pragma unroll
    for (int j = 0; j < D / 32; j++) {
        int c = lane + j * 32;
        float v = h[(size_t)w * D + c];
        sf += v * a[c];
        sg += v * a[D + c];
    }
#pragma unroll
    for (int o = 16; o; o >>= 1) {
        sf += __shfl_xor_sync(0xffffffffu, sf, o);
        sg += __shfl_xor_sync(0xffffffffu, sg, o);
    }
    if (lane == 0) { f[w] = sf; g[w] = sg; }
}

// ---------------- CSR build ----------------
__global__ void count_k(const int* __restrict__ rows, int* __restrict__ cnt) {
    int e = blockIdx.x * blockDim.x + threadIdx.x;
    if (e < EDGES) atomicAdd(&cnt[rows[e]], 1);
}

__global__ void scan_block_k(const int* __restrict__ in, int* __restrict__ incl,
                             int* __restrict__ bsums, int n) {
    __shared__ int sm[1024];
    int i = blockIdx.x * 1024 + threadIdx.x;
    int v = (i < n) ? in[i] : 0;
    sm[threadIdx.x] = v;
    __syncthreads();
#pragma unroll
    for (int o = 1; o < 1024; o <<= 1) {
        int t = (threadIdx.x >= o) ? sm[threadIdx.x - o] : 0;
        __syncthreads();
        sm[threadIdx.x] += t;
        __syncthreads();
    }
    if (i < n) incl[i] = sm[threadIdx.x];
    if (threadIdx.x == 1023) bsums[blockIdx.x] = sm[1023];
}

__global__ void scan_sums_k(const int* __restrict__ bsums, int* __restrict__ bpre, int nb) {
    if (blockIdx.x == 0 && threadIdx.x == 0) {
        int run = 0;
        for (int i = 0; i < nb; i++) { bpre[i] = run; run += bsums[i]; }
    }
}

__global__ void finalize_csr_k(const int* __restrict__ incl, const int* __restrict__ cnt,
                               const int* __restrict__ bpre, int* __restrict__ rowptr,
                               int* __restrict__ tmp) {
    int i = blockIdx.x * blockDim.x + threadIdx.x;
    if (i < NROWS) {
        int ex = incl[i] - cnt[i] + bpre[i >> 10];
        rowptr[i] = ex;
        tmp[i] = ex;
    }
    if (i == 0) rowptr[NROWS] = EDGES;
}

__global__ void scatter_k(const int* __restrict__ rows, const int* __restrict__ cols_in,
                          int* __restrict__ tmp, int* __restrict__ cols_out) {
    int e = blockIdx.x * blockDim.x + threadIdx.x;
    if (e < EDGES) {
        int r = rows[e];
        int p = atomicAdd(&tmp[r], 1);
        cols_out[p] = cols_in[e];
    }
}

// ---------------- SpGAT aggregation: out[r] = elu( sum_e w*h[col] / (sum_e w + eps) ) ----------------
template <int D>
__global__ void agg_k(const int* __restrict__ rowptr, const int* __restrict__ cols,
                      const float* __restrict__ f, const float* __restrict__ g,
                      const float* __restrict__ h, float* __restrict__ out) {
    int row = (blockIdx.x * blockDim.x + threadIdx.x) >> 5;
    int lane = threadIdx.x & 31;
    if (row >= NROWS) return;
    int s = rowptr[row];
    int e = rowptr[row + 1];
    float fr = f[row];
    constexpr int V = D / 32;
    float acc[V];
#pragma unroll
    for (int j = 0; j < V; j++) acc[j] = 0.0f;
    float den = 0.0f;
    for (int p = s; p < e; p++) {
        int c = cols[p];
        float x = fr + g[c];
        float lr = x > 0.0f ? x : ALPHA * x;
        float w = expf(-lr);
        den += w;
        const float* hc = h + (size_t)c * D;
#pragma unroll
        for (int j = 0; j < V; j++) acc[j] += w * hc[lane + j * 32];
    }
    float inv = 1.0f / (den + EPSV);
#pragma unroll
    for (int j = 0; j < V; j++) {
        float v = acc[j] * inv;
        v = v > 0.0f ? v : expm1f(v);   // ELU (alpha=1)
        out[(size_t)row * D + lane + j * 32] = v;
    }
}

// ---------------- final fusion + classifier + log_softmax ----------------
__global__ void final_k(const float* __restrict__ twX, const float* __restrict__ tuX,
                        const int* __restrict__ g0, const int* __restrict__ g1,
                        const float* __restrict__ outW, const float* __restrict__ outB,
                        const float* __restrict__ att, float* __restrict__ out) {
    int b = (blockIdx.x * blockDim.x + threadIdx.x) >> 5;
    int lane = threadIdx.x & 31;
    if (b >= BATCH) return;
    float a0 = att[0] * (1.0f / NROWS);
    float a1 = att[1] * (1.0f / NROWS);
    float mx = fmaxf(a0, a1);
    float e0 = expf(a0 - mx), e1 = expf(a1 - mx);
    float inv = 1.0f / (e0 + e1);
    float w0 = e0 * inv, w1 = e1 * inv;
    int i0 = g0[b], i1 = g1[b];
    float l0 = 0.0f, l1 = 0.0f;
#pragma unroll
    for (int j = 0; j < JOINT / 32; j++) {
        int c = lane + j * 32;
        float fv = w0 * twX[(size_t)i0 * JOINT + c] + w1 * tuX[(size_t)i1 * JOINT + c];
        l0 += fv * outW[c];
        l1 += fv * outW[JOINT + c];
    }
#pragma unroll
    for (int o = 16; o; o >>= 1) {
        l0 += __shfl_xor_sync(0xffffffffu, l0, o);
        l1 += __shfl_xor_sync(0xffffffffu, l1, o);
    }
    if (lane == 0) {
        l0 += outB[0];
        l1 += outB[1];
        float m = fmaxf(l0, l1);
        float lse = m + logf(expf(l0 - m) + expf(l1 - m));
        out[b * 2 + 0] = l0 - lse;
        out[b * 2 + 1] = l1 - lse;
    }
}

// ---------------- host launcher ----------------
static void build_csr(const int* edges) {
    int* cnt;    cudaGetSymbolAddress((void**)&cnt, g_cnt);
    int* incl;   cudaGetSymbolAddress((void**)&incl, g_incl);
    int* rowptr; cudaGetSymbolAddress((void**)&rowptr, g_rowptr);
    int* tmp;    cudaGetSymbolAddress((void**)&tmp, g_tmp);
    int* cols;   cudaGetSymbolAddress((void**)&cols, g_cols);
    int* bsums;  cudaGetSymbolAddress((void**)&bsums, g_bsums);
    int* bpre;   cudaGetSymbolAddress((void**)&bpre, g_bpre);

    int nb = (NROWS + 1023) / 1024;  // 49
    zero_int_k<<<(NROWS + 255) / 256, 256>>>(cnt, NROWS);
    count_k<<<(EDGES + 255) / 256, 256>>>(edges, cnt);
    scan_block_k<<<nb, 1024>>>(cnt, incl, bsums, NROWS);
    scan_sums_k<<<1, 32>>>(bsums, bpre, nb);
    finalize_csr_k<<<(NROWS + 255) / 256, 256>>>(incl, cnt, bpre, rowptr, tmp);
    scatter_k<<<(EDGES + 255) / 256, 256>>>(edges, edges + EDGES, tmp, cols);
}

extern "C" void kernel_launch(void* const* d_in, const int* in_sizes, int n_in,
                              void* d_out, int out_size) {
    const float *word_emb, *user_emb, *tw_W1, *tw_a1, *tw_W2, *tw_a2;
    const float *tu_W1, *tu_a1, *tu_W2, *tu_a2, *weight_W, *weight_proj, *out_W, *out_b;
    const int *feat_idx, *tw_edges, *ut_edges, *tw_gidx, *ut_gidx;

    if (in_sizes[0] == NROWS * NFEAT) {
        // reference() signature order
        word_emb    = (const float*)d_in[0];
        user_emb    = (const float*)d_in[1];
        tw_W1       = (const float*)d_in[2];
        tw_a1       = (const float*)d_in[3];
        tw_W2       = (const float*)d_in[4];
        tw_a2       = (const float*)d_in[5];
        tu_W1       = (const float*)d_in[6];
        tu_a1       = (const float*)d_in[7];
        tu_W2       = (const float*)d_in[8];
        tu_a2       = (const float*)d_in[9];
        weight_W    = (const float*)d_in[10];
        weight_proj = (const float*)d_in[11];
        out_W       = (const float*)d_in[12];
        out_b       = (const float*)d_in[13];
        feat_idx    = (const int*)d_in[14];
        tw_edges    = (const int*)d_in[15];
        ut_edges    = (const int*)d_in[16];
        tw_gidx     = (const int*)d_in[17];
        ut_gidx     = (const int*)d_in[18];
    } else {
        // setup_inputs() dict order
        feat_idx    = (const int*)d_in[0];
        tw_edges    = (const int*)d_in[1];
        ut_edges    = (const int*)d_in[2];
        tw_gidx     = (const int*)d_in[3];
        ut_gidx     = (const int*)d_in[4];
        word_emb    = (const float*)d_in[5];
        user_emb    = (const float*)d_in[6];
        tw_W1       = (const float*)d_in[7];
        tw_a1       = (const float*)d_in[8];
        tw_W2       = (const float*)d_in[9];
        tw_a2       = (const float*)d_in[10];
        tu_W1       = (const float*)d_in[11];
        tu_a1       = (const float*)d_in[12];
        tu_W2       = (const float*)d_in[13];
        tu_a2       = (const float*)d_in[14];
        weight_W    = (const float*)d_in[15];
        weight_proj = (const float*)d_in[16];
        out_W       = (const float*)d_in[17];
        out_b       = (const float*)d_in[18];
    }

    float *bufA, *bufB, *bufC, *twX, *tuX, *fv, *gv, *att;
    int *rowptr, *cols;
    cudaGetSymbolAddress((void**)&bufA, g_bufA);
    cudaGetSymbolAddress((void**)&bufB, g_bufB);
    cudaGetSymbolAddress((void**)&bufC, g_bufC);
    cudaGetSymbolAddress((void**)&twX, g_twX);
    cudaGetSymbolAddress((void**)&tuX, g_tuX);
    cudaGetSymbolAddress((void**)&fv, g_fv);
    cudaGetSymbolAddress((void**)&gv, g_gv);
    cudaGetSymbolAddress((void**)&att, g_att);
    cudaGetSymbolAddress((void**)&rowptr, g_rowptr);
    cudaGetSymbolAddress((void**)&cols, g_cols);

    const int WARPS_GRID = (NROWS * 32 + 255) / 256;   // 6250 blocks of 8 warps
    const int G1 = (NROWS + 127) / 128;                 // 391
    const int G2 = (NROWS + 63) / 64;                   // 782

    zero_att_k<<<1, 32>>>(att);

    // ================= tweet view =================
    // Pw = word_emb @ tw_W1   [VOCAB=NROWS, 64]
    gemm_k<128, 64, 32, 8, 4, false><<<G1, 256>>>(word_emb, tw_W1, bufA, NROWS, NFEAT, nullptr, nullptr);
    // h1 = mean over 16 words of Pw rows
    gather_mean_k<<<(NROWS + 3) / 4, dim3(64, 4)>>>(feat_idx, bufA, bufB);
    fg_k<HID><<<WARPS_GRID, 256>>>(bufB, tw_a1, fv, gv);
    build_csr(tw_edges);
    agg_k<HID><<<WARPS_GRID, 256>>>(rowptr, cols, fv, gv, bufB, bufA);          // out1 -> bufA
    gemm_k<64, 128, 32, 4, 8, false><<<G2, 256>>>(bufA, tw_W2, bufC, NROWS, HID, nullptr, nullptr);
    fg_k<JOINT><<<WARPS_GRID, 256>>>(bufC, tw_a2, fv, gv);
    agg_k<JOINT><<<WARPS_GRID, 256>>>(rowptr, cols, fv, gv, bufC, twX);
    gemm_k<64, 128, 32, 4, 8, true><<<G2, 256>>>(twX, weight_W, nullptr, NROWS, JOINT, weight_proj, att + 0);

    // ================= user view =================
    gemm_k<128, 64, 32, 8, 4, false><<<G1, 256>>>(user_emb, tu_W1, bufA, NROWS, NFEAT, nullptr, nullptr);
    fg_k<HID><<<WARPS_GRID, 256>>>(bufA, tu_a1, fv, gv);
    build_csr(ut_edges);
    agg_k<HID><<<WARPS_GRID, 256>>>(rowptr, cols, fv, gv, bufA, bufB);          // out1 -> bufB
    gemm_k<64, 128, 32, 4, 8, false><<<G2, 256>>>(bufB, tu_W2, bufC, NROWS, HID, nullptr, nullptr);
    fg_k<JOINT><<<WARPS_GRID, 256>>>(bufC, tu_a2, fv, gv);
    agg_k<JOINT><<<WARPS_GRID, 256>>>(rowptr, cols, fv, gv, bufC, tuX);
    gemm_k<64, 128, 32, 4, 8, true><<<G2, 256>>>(tuX, weight_W, nullptr, NROWS, JOINT, weight_proj, att + 1);

    // ================= fusion + classifier =================
    final_k<<<(BATCH * 32 + 255) / 256, 256>>>(twX, tuX, tw_gidx, ut_gidx, out_W, out_b, att, (float*)d_out);
}